// round 1
// baseline (speedup 1.0000x reference)
#include <cuda_runtime.h>
#include <cuda_bf16.h>
#include <cstdint>

#define T_DIM 512
#define B_DIM 16
#define D_DIM 1024
#define WIN   16
#define WSZ   33          // window size = 2*WIN+1
#define TT    32          // t-tile per block in attn kernel
#define DC    256         // d-chunk per block in attn kernel

// Scratch (no cudaMalloc allowed)
__device__ float g_a[T_DIM * B_DIM];
__device__ float g_c[T_DIM * B_DIM];
__device__ float g_p[B_DIM * T_DIM * WSZ];   // layout [b][t][w], contiguous per (b,t)

// ---------------------------------------------------------------------------
// Kernel A: per-row dot products a = x·w_cur, c = x·w_seq, and copy x -> out[:D]
// One warp per (t,b) row. 1024 blocks x 256 threads = 8192 warps.
// ---------------------------------------------------------------------------
__global__ void k_dots(const float* __restrict__ x, const float* __restrict__ w,
                       float* __restrict__ out) {
    int warp = (blockIdx.x << 3) + (threadIdx.x >> 5);   // row r = t*16 + b
    int lane = threadIdx.x & 31;
    const float4* xr = reinterpret_cast<const float4*>(x) + (size_t)warp * 256;
    const float4* wc = reinterpret_cast<const float4*>(w);
    const float4* ws = wc + 256;
    float4* oc = reinterpret_cast<float4*>(out) + (size_t)warp * 512;

    float sa = 0.f, sc = 0.f;
#pragma unroll
    for (int i = 0; i < 8; i++) {
        int k = lane + i * 32;
        float4 xv = xr[k];
        float4 a4 = wc[k];
        float4 c4 = ws[k];
        sa += xv.x * a4.x + xv.y * a4.y + xv.z * a4.z + xv.w * a4.w;
        sc += xv.x * c4.x + xv.y * c4.y + xv.z * c4.z + xv.w * c4.w;
        oc[k] = xv;                         // out[t,b,0:D] = x
    }
#pragma unroll
    for (int off = 16; off; off >>= 1) {
        sa += __shfl_xor_sync(0xFFFFFFFFu, sa, off);
        sc += __shfl_xor_sync(0xFFFFFFFFu, sc, off);
    }
    if (lane == 0) { g_a[warp] = sa; g_c[warp] = sc; }
}

// ---------------------------------------------------------------------------
// Kernel B: softmax over the 33-tap window for each (t,b).
// One thread per (t,b); b is the fast index for coalesced g_c reads.
// ---------------------------------------------------------------------------
__global__ void k_soft(const float* __restrict__ bb) {
    int g = blockIdx.x * 256 + threadIdx.x;   // g = t*16 + b
    int b = g & 15;
    int t = g >> 4;
    float base = g_a[g] + bb[0];

    float s[WSZ];
    float m = -INFINITY;
#pragma unroll
    for (int wi = 0; wi < WSZ; wi++) {
        int idx = t - WIN + wi;
        float v = (idx >= 0 && idx < T_DIM) ? base + g_c[idx * B_DIM + b] : -INFINITY;
        s[wi] = v;
        m = fmaxf(m, v);
    }
    float sum = 0.f;
#pragma unroll
    for (int wi = 0; wi < WSZ; wi++) {
        float e = (s[wi] == -INFINITY) ? 0.f : __expf(s[wi] - m);
        s[wi] = e;
        sum += e;
    }
    float inv = 1.f / sum;
    float* pr = g_p + ((size_t)b * T_DIM + t) * WSZ;
#pragma unroll
    for (int wi = 0; wi < WSZ; wi++) pr[wi] = s[wi] * inv;
}

// ---------------------------------------------------------------------------
// Kernel C: windowed weighted sum.
//   attn[t,b,d] = sum_w p[t,w]*x[clip(t-16+w),b,d]
// Block = (d-chunk of 256, t-tile of 32, b). Smem: x tile (64 rows x 256 f)
// + diagonal-packed duplicated p: pd[row][tl] = {p,p} where row = tl + w.
// Thread: fixed float4 d-column, 8 consecutive t accumulators, f32x2 FMAs.
// ---------------------------------------------------------------------------
__device__ __forceinline__ void fma2(unsigned long long& a,
                                     unsigned long long xv,
                                     unsigned long long pp) {
    asm("fma.rn.f32x2 %0, %1, %2, %0;" : "+l"(a) : "l"(xv), "l"(pp));
}
__device__ __forceinline__ float2 u2f(unsigned long long v) {
    float2 r;
    asm("mov.b64 {%0,%1}, %2;" : "=f"(r.x), "=f"(r.y) : "l"(v));
    return r;
}

__global__ void k_attn(const float* __restrict__ x, float* __restrict__ out) {
    extern __shared__ float smem[];
    float*  xs = smem;                                  // 64*256 floats = 64KB
    float2* pd = reinterpret_cast<float2*>(smem + (TT + 2 * WIN) * DC); // 64*32 float2 = 16KB

    const int tid = threadIdx.x;
    const int d0 = blockIdx.x * DC;
    const int t0 = blockIdx.y * TT;
    const int b  = blockIdx.z;

    // zero-init pd (entries never scattered must be exactly 0)
#pragma unroll
    for (int i = tid; i < (TT + 2 * WIN) * TT; i += 256)
        pd[i] = make_float2(0.f, 0.f);
    __syncthreads();

    // load x tile: rows t0-16 .. t0+47 (clamped; clamped rows get weight 0)
    const float4* x4 = reinterpret_cast<const float4*>(x);
    float4* xs4 = reinterpret_cast<float4*>(xs);
#pragma unroll
    for (int k = 0; k < 16; k++) {
        int idx = tid + k * 256;
        int row = idx >> 6;
        int col = idx & 63;
        int gr = t0 - WIN + row;
        gr = gr < 0 ? 0 : (gr > T_DIM - 1 ? T_DIM - 1 : gr);
        xs4[idx] = x4[((size_t)gr * B_DIM + b) * (D_DIM / 4) + (d0 >> 2) + col];
    }

    // scatter p diagonally, pre-duplicated: pd[tl+w][tl] = {p,p}
    const float* pr = g_p + ((size_t)b * T_DIM + t0) * WSZ;
    for (int idx = tid; idx < TT * WSZ; idx += 256) {
        int tl = idx / WSZ;
        int wi = idx - tl * WSZ;
        float p = pr[idx];
        pd[(tl + wi) * TT + tl] = make_float2(p, p);
    }
    __syncthreads();

    const int d4 = tid & 63;    // float4 column
    const int tg = tid >> 6;    // which 8-t group
    const int tb = tg * 8;

    unsigned long long acc[16];
#pragma unroll
    for (int j = 0; j < 16; j++) acc[j] = 0ULL;

    const ulonglong2* xsq = reinterpret_cast<const ulonglong2*>(xs);
    const ulonglong2* pdq = reinterpret_cast<const ulonglong2*>(pd);

#pragma unroll
    for (int r = 0; r < 40; r++) {
        int row = tb + r;
        ulonglong2 xv = xsq[row * 64 + d4];         // x[row][d4*4 .. +3]
        int pbase = row * 16 + tg * 4;              // pd[row][tb .. tb+7] as 4x ull2
        ulonglong2 q0 = pdq[pbase + 0];
        ulonglong2 q1 = pdq[pbase + 1];
        ulonglong2 q2 = pdq[pbase + 2];
        ulonglong2 q3 = pdq[pbase + 3];
        fma2(acc[0],  xv.x, q0.x); fma2(acc[1],  xv.y, q0.x);
        fma2(acc[2],  xv.x, q0.y); fma2(acc[3],  xv.y, q0.y);
        fma2(acc[4],  xv.x, q1.x); fma2(acc[5],  xv.y, q1.x);
        fma2(acc[6],  xv.x, q1.y); fma2(acc[7],  xv.y, q1.y);
        fma2(acc[8],  xv.x, q2.x); fma2(acc[9],  xv.y, q2.x);
        fma2(acc[10], xv.x, q2.y); fma2(acc[11], xv.y, q2.y);
        fma2(acc[12], xv.x, q3.x); fma2(acc[13], xv.y, q3.x);
        fma2(acc[14], xv.x, q3.y); fma2(acc[15], xv.y, q3.y);
    }

    float4* o4 = reinterpret_cast<float4*>(out);
#pragma unroll
    for (int j = 0; j < 8; j++) {
        int t = t0 + tb + j;
        float2 lo = u2f(acc[2 * j]);
        float2 hi = u2f(acc[2 * j + 1]);
        o4[((size_t)t * B_DIM + b) * (2 * D_DIM / 4) + (D_DIM / 4) + (d0 >> 2) + d4] =
            make_float4(lo.x, lo.y, hi.x, hi.y);
    }
}

// ---------------------------------------------------------------------------
extern "C" void kernel_launch(void* const* d_in, const int* in_sizes, int n_in,
                              void* d_out, int out_size) {
    const float* x  = reinterpret_cast<const float*>(d_in[0]);
    const float* w  = reinterpret_cast<const float*>(d_in[1]);
    const float* bb = reinterpret_cast<const float*>(d_in[2]);
    float* out = reinterpret_cast<float*>(d_out);

    const int smem_bytes = ((TT + 2 * WIN) * DC) * 4 + ((TT + 2 * WIN) * TT) * 8; // 64KB + 16KB
    cudaFuncSetAttribute(k_attn, cudaFuncAttributeMaxDynamicSharedMemorySize, smem_bytes);

    k_dots<<<(T_DIM * B_DIM) / 8, 256>>>(x, w, out);
    k_soft<<<(T_DIM * B_DIM) / 256, 256>>>(bb);
    dim3 grid(D_DIM / DC, T_DIM / TT, B_DIM);
    k_attn<<<grid, 256, smem_bytes>>>(x, out);
}

// round 2
// speedup vs baseline: 1.3599x; 1.3599x over previous
#include <cuda_runtime.h>
#include <cuda_bf16.h>
#include <cstdint>

#define T_DIM 512
#define B_DIM 16
#define D_DIM 1024
#define WIN   16
#define WSZ   33          // window taps = 2*WIN+1
#define TT    32          // t-tile per block in attn kernel
#define DC    256         // d-chunk (floats) per block in attn kernel
#define HR    (TT + 2*WIN) // halo rows = 64

// Scratch (no cudaMalloc allowed)
__device__ float g_a[T_DIM * B_DIM];
__device__ float g_c[T_DIM * B_DIM];

// ---------------------------------------------------------------------------
// Kernel A: a = x·w_cur, c = x·w_seq per (t,b) row, and copy x -> out[:, :, :D]
// One warp per row. out written with .cs (evict-first) so x stays L2-resident.
// ---------------------------------------------------------------------------
__global__ void k_dots(const float* __restrict__ x, const float* __restrict__ w,
                       float* __restrict__ out) {
    int warp = (blockIdx.x << 3) + (threadIdx.x >> 5);   // row r = t*16 + b
    int lane = threadIdx.x & 31;
    const float4* xr = reinterpret_cast<const float4*>(x) + (size_t)warp * 256;
    const float4* wc = reinterpret_cast<const float4*>(w);
    const float4* ws = wc + 256;
    float4* oc = reinterpret_cast<float4*>(out) + (size_t)warp * 512;

    float sa = 0.f, sc = 0.f;
#pragma unroll
    for (int i = 0; i < 8; i++) {
        int k = lane + i * 32;
        float4 xv = xr[k];
        float4 a4 = wc[k];
        float4 c4 = ws[k];
        sa += xv.x * a4.x + xv.y * a4.y + xv.z * a4.z + xv.w * a4.w;
        sc += xv.x * c4.x + xv.y * c4.y + xv.z * c4.z + xv.w * c4.w;
        __stcs(&oc[k], xv);                 // out[t,b,0:D] = x, streaming
    }
#pragma unroll
    for (int off = 16; off; off >>= 1) {
        sa += __shfl_xor_sync(0xFFFFFFFFu, sa, off);
        sc += __shfl_xor_sync(0xFFFFFFFFu, sc, off);
    }
    if (lane == 0) { g_a[warp] = sa; g_c[warp] = sc; }
}

// ---------------------------------------------------------------------------
// packed f32x2 helpers
// ---------------------------------------------------------------------------
__device__ __forceinline__ void fma2(unsigned long long& a,
                                     unsigned long long xv,
                                     unsigned long long pp) {
    asm("fma.rn.f32x2 %0, %1, %2, %0;" : "+l"(a) : "l"(xv), "l"(pp));
}
__device__ __forceinline__ float2 u2f(unsigned long long v) {
    float2 r;
    asm("mov.b64 {%0,%1}, %2;" : "=f"(r.x), "=f"(r.y) : "l"(v));
    return r;
}
__device__ __forceinline__ void cp16(void* s, const void* g) {
    unsigned sa = (unsigned)__cvta_generic_to_shared(s);
    asm volatile("cp.async.cg.shared.global [%0], [%1], 16;" :: "r"(sa), "l"(g));
}
__device__ __forceinline__ void cp_commit() {
    asm volatile("cp.async.commit_group;");
}
template <int N>
__device__ __forceinline__ void cp_wait() {
    asm volatile("cp.async.wait_group %0;" :: "n"(N));
}

// ---------------------------------------------------------------------------
// Kernel B (fused softmax + windowed sum):
//   attn[t,b,d] = sum_w softmax_w(a[t,b]+c[t-16+w,b]+b0) * x[clip(t-16+w),b,d]
// Block = (d-chunk 256, t-tile 32, b). Pipeline: 4 cp.async stages of 16 rows
// overlap with in-block softmax (warp 0) and the staged FMA loop.
// ---------------------------------------------------------------------------
__global__ void k_attn(const float* __restrict__ x, const float* __restrict__ bb,
                       float* __restrict__ out) {
    extern __shared__ float smem[];
    float*  xs = smem;                                        // 64*256 f = 64KB
    float2* pd = reinterpret_cast<float2*>(smem + HR * DC);   // 64*32 f2 = 16KB

    const int tid = threadIdx.x;
    const int d0 = blockIdx.x * DC;
    const int t0 = blockIdx.y * TT;
    const int b  = blockIdx.z;

    // ---- issue all 4 cp.async stages first (16 rows each) ----
    const float4* x4 = reinterpret_cast<const float4*>(x);
    float4* xs4 = reinterpret_cast<float4*>(xs);
#pragma unroll
    for (int s = 0; s < 4; s++) {
#pragma unroll
        for (int k = 0; k < 4; k++) {
            int idx = s * 1024 + k * 256 + tid;
            int row = idx >> 6;
            int col = idx & 63;
            int gr = t0 - WIN + row;
            gr = gr < 0 ? 0 : (gr > T_DIM - 1 ? T_DIM - 1 : gr);
            cp16(&xs4[idx], &x4[((size_t)gr * B_DIM + b) * (D_DIM / 4) + (d0 >> 2) + col]);
        }
        cp_commit();
    }

    // ---- zero pd while loads are in flight ----
#pragma unroll
    for (int i = tid; i < HR * TT; i += 256)
        pd[i] = make_float2(0.f, 0.f);
    __syncthreads();

    // ---- warp 0: softmax for the 32 t's, scatter diagonally into pd ----
    if (tid < 32) {
        const int tl = tid;
        const int t = t0 + tl;
        const float base = g_a[t * B_DIM + b] + bb[0];
        float sv[WSZ];
        float m = -INFINITY;
#pragma unroll
        for (int wi = 0; wi < WSZ; wi++) {
            int idx = t - WIN + wi;
            bool valid = (idx >= 0) && (idx < T_DIM);
            float v = valid ? base + g_c[idx * B_DIM + b] : -INFINITY;
            sv[wi] = v;
            m = fmaxf(m, v);
        }
        float sum = 0.f;
#pragma unroll
        for (int wi = 0; wi < WSZ; wi++) {
            float e = (sv[wi] == -INFINITY) ? 0.f : __expf(sv[wi] - m);
            sv[wi] = e;
            sum += e;
        }
        float inv = 1.f / sum;
#pragma unroll
        for (int wi = 0; wi < WSZ; wi++) {
            float p = sv[wi] * inv;
            pd[(tl + wi) * TT + tl] = make_float2(p, p);
        }
    }

    const int d4 = tid & 63;    // float4 column within d-chunk
    const int tg = tid >> 6;    // t-group (8 t's each)
    const int tb = tg * 8;

    unsigned long long acc[16];
#pragma unroll
    for (int j = 0; j < 16; j++) acc[j] = 0ULL;

    const ulonglong2* xsq = reinterpret_cast<const ulonglong2*>(xs);
    const ulonglong2* pdq = reinterpret_cast<const ulonglong2*>(pd);

#define ROW_STEP(r)                                                     \
    {                                                                   \
        int row = tb + (r);                                             \
        ulonglong2 xv = xsq[row * 64 + d4];                             \
        int pbase = row * 16 + tg * 4;                                  \
        ulonglong2 q0 = pdq[pbase + 0];                                 \
        ulonglong2 q1 = pdq[pbase + 1];                                 \
        ulonglong2 q2 = pdq[pbase + 2];                                 \
        ulonglong2 q3 = pdq[pbase + 3];                                 \
        fma2(acc[0],  xv.x, q0.x); fma2(acc[1],  xv.y, q0.x);           \
        fma2(acc[2],  xv.x, q0.y); fma2(acc[3],  xv.y, q0.y);           \
        fma2(acc[4],  xv.x, q1.x); fma2(acc[5],  xv.y, q1.x);           \
        fma2(acc[6],  xv.x, q1.y); fma2(acc[7],  xv.y, q1.y);           \
        fma2(acc[8],  xv.x, q2.x); fma2(acc[9],  xv.y, q2.x);           \
        fma2(acc[10], xv.x, q2.y); fma2(acc[11], xv.y, q2.y);           \
        fma2(acc[12], xv.x, q3.x); fma2(acc[13], xv.y, q3.x);           \
        fma2(acc[14], xv.x, q3.y); fma2(acc[15], xv.y, q3.y);           \
    }

    // rows needed at step r: up to 24+r. Stage s covers rows [16s, 16s+15].
    cp_wait<2>();            // stages 0,1 complete (rows 0..31)
    __syncthreads();         // pd scatter + stage data visible to all
#pragma unroll
    for (int r = 0; r < 8; r++) ROW_STEP(r);

    cp_wait<1>();            // stage 2 (rows 32..47)
    __syncthreads();
#pragma unroll
    for (int r = 8; r < 24; r++) ROW_STEP(r);

    cp_wait<0>();            // stage 3 (rows 48..63)
    __syncthreads();
#pragma unroll
    for (int r = 24; r < 40; r++) ROW_STEP(r);
#undef ROW_STEP

    float4* o4 = reinterpret_cast<float4*>(out);
#pragma unroll
    for (int j = 0; j < 8; j++) {
        int t = t0 + tb + j;
        float2 lo = u2f(acc[2 * j]);
        float2 hi = u2f(acc[2 * j + 1]);
        __stcs(&o4[((size_t)t * B_DIM + b) * (2 * D_DIM / 4) + (D_DIM / 4) + (d0 >> 2) + d4],
               make_float4(lo.x, lo.y, hi.x, hi.y));
    }
}

// ---------------------------------------------------------------------------
extern "C" void kernel_launch(void* const* d_in, const int* in_sizes, int n_in,
                              void* d_out, int out_size) {
    const float* x  = reinterpret_cast<const float*>(d_in[0]);
    const float* w  = reinterpret_cast<const float*>(d_in[1]);
    const float* bb = reinterpret_cast<const float*>(d_in[2]);
    float* out = reinterpret_cast<float*>(d_out);

    const int smem_bytes = HR * DC * 4 + HR * TT * 8;   // 64KB + 16KB
    cudaFuncSetAttribute(k_attn, cudaFuncAttributeMaxDynamicSharedMemorySize, smem_bytes);

    k_dots<<<(T_DIM * B_DIM) / 8, 256>>>(x, w, out);
    dim3 grid(D_DIM / DC, T_DIM / TT, B_DIM);
    k_attn<<<grid, 256, smem_bytes>>>(x, bb, out);
}

// round 3
// speedup vs baseline: 1.6096x; 1.1837x over previous
#include <cuda_runtime.h>
#include <cuda_bf16.h>
#include <cstdint>

#define T_DIM 512
#define B_DIM 16
#define D_DIM 1024
#define WIN   16
#define WSZ   33           // window taps = 2*WIN+1
#define TT    32           // t-tile per block in attn kernel
#define DC    256          // d-chunk (floats) per block in attn kernel
#define HR    (TT + 2*WIN) // halo rows = 64

// Scratch (no cudaMalloc allowed)
__device__ float g_a[T_DIM * B_DIM];
__device__ float g_c[T_DIM * B_DIM];

// ---------------------------------------------------------------------------
// Kernel A: pure dot products a = x·w_cur, c = x·w_seq per (t,b) row.
// One warp per row; read-only streaming (x left L2-resident for k_attn).
// ---------------------------------------------------------------------------
__global__ void k_dots(const float* __restrict__ x, const float* __restrict__ w) {
    int warp = (blockIdx.x << 3) + (threadIdx.x >> 5);   // row r = t*16 + b
    int lane = threadIdx.x & 31;
    const float4* xr = reinterpret_cast<const float4*>(x) + (size_t)warp * 256;
    const float4* wc = reinterpret_cast<const float4*>(w);
    const float4* ws = wc + 256;

    float4 xv[8];
#pragma unroll
    for (int i = 0; i < 8; i++) xv[i] = xr[lane + i * 32];   // front-load, MLP=8

    float sa = 0.f, sc = 0.f;
#pragma unroll
    for (int i = 0; i < 8; i++) {
        int k = lane + i * 32;
        float4 a4 = __ldg(&wc[k]);
        float4 c4 = __ldg(&ws[k]);
        sa += xv[i].x * a4.x + xv[i].y * a4.y + xv[i].z * a4.z + xv[i].w * a4.w;
        sc += xv[i].x * c4.x + xv[i].y * c4.y + xv[i].z * c4.z + xv[i].w * c4.w;
    }
#pragma unroll
    for (int off = 16; off; off >>= 1) {
        sa += __shfl_xor_sync(0xFFFFFFFFu, sa, off);
        sc += __shfl_xor_sync(0xFFFFFFFFu, sc, off);
    }
    if (lane == 0) { g_a[warp] = sa; g_c[warp] = sc; }
}

// ---------------------------------------------------------------------------
// packed f32x2 helpers
// ---------------------------------------------------------------------------
__device__ __forceinline__ void fma2(unsigned long long& a,
                                     unsigned long long xv,
                                     unsigned long long pp) {
    asm("fma.rn.f32x2 %0, %1, %2, %0;" : "+l"(a) : "l"(xv), "l"(pp));
}
__device__ __forceinline__ float2 u2f(unsigned long long v) {
    float2 r;
    asm("mov.b64 {%0,%1}, %2;" : "=f"(r.x), "=f"(r.y) : "l"(v));
    return r;
}
__device__ __forceinline__ unsigned long long dup2(float p) {
    unsigned long long u;
    asm("mov.b64 %0, {%1, %1};" : "=l"(u) : "f"(p));
    return u;
}
__device__ __forceinline__ void cp16(void* s, const void* g) {
    unsigned sa = (unsigned)__cvta_generic_to_shared(s);
    asm volatile("cp.async.cg.shared.global [%0], [%1], 16;" :: "r"(sa), "l"(g));
}
__device__ __forceinline__ void cp_commit() {
    asm volatile("cp.async.commit_group;");
}
template <int N>
__device__ __forceinline__ void cp_wait() {
    asm volatile("cp.async.wait_group %0;" :: "n"(N));
}

// ---------------------------------------------------------------------------
// Kernel B (fused softmax + windowed sum + x-copy):
//   out[t,b,0:D]    = x[t,b,:]                        (written from xv regs)
//   out[t,b,D:2D]   = sum_w softmax * x[clip(t-16+w)]
// Block = (d-chunk 256, t-tile 32, b). 4-stage cp.async pipeline.
// pd stored as scalar float (8KB) -> 72KB smem -> 3 CTAs/SM.
// ---------------------------------------------------------------------------
__global__ void __launch_bounds__(256, 3)
k_attn(const float* __restrict__ x, const float* __restrict__ bb,
       float* __restrict__ out) {
    extern __shared__ float smem[];
    float* xs = smem;                    // 64*256 f = 64KB
    float* pd = smem + HR * DC;          // 64*32 f = 8KB; pd[row*TT + tl]

    const int tid = threadIdx.x;
    const int d0 = blockIdx.x * DC;
    const int t0 = blockIdx.y * TT;
    const int b  = blockIdx.z;

    // ---- issue all 4 cp.async stages (16 rows each) ----
    const float4* x4 = reinterpret_cast<const float4*>(x);
    float4* xs4 = reinterpret_cast<float4*>(xs);
#pragma unroll
    for (int s = 0; s < 4; s++) {
#pragma unroll
        for (int k = 0; k < 4; k++) {
            int idx = s * 1024 + k * 256 + tid;
            int row = idx >> 6;
            int col = idx & 63;
            int gr = t0 - WIN + row;
            gr = gr < 0 ? 0 : (gr > T_DIM - 1 ? T_DIM - 1 : gr);
            cp16(&xs4[idx], &x4[((size_t)gr * B_DIM + b) * (D_DIM / 4) + (d0 >> 2) + col]);
        }
        cp_commit();
    }

    // ---- zero pd while loads are in flight ----
#pragma unroll
    for (int i = tid; i < HR * TT; i += 256) pd[i] = 0.f;
    __syncthreads();

    // ---- warp 0: softmax for the 32 t's, scatter diagonally into pd ----
    if (tid < 32) {
        const int tl = tid;
        const int t = t0 + tl;
        const float base = g_a[t * B_DIM + b] + bb[0];
        float sv[WSZ];
        float m = -INFINITY;
#pragma unroll
        for (int wi = 0; wi < WSZ; wi++) {
            int idx = t - WIN + wi;
            bool valid = (idx >= 0) && (idx < T_DIM);
            float v = valid ? base + g_c[idx * B_DIM + b] : -INFINITY;
            sv[wi] = v;
            m = fmaxf(m, v);
        }
        float sum = 0.f;
#pragma unroll
        for (int wi = 0; wi < WSZ; wi++) {
            float e = (sv[wi] == -INFINITY) ? 0.f : __expf(sv[wi] - m);
            sv[wi] = e;
            sum += e;
        }
        float inv = 1.f / sum;
#pragma unroll
        for (int wi = 0; wi < WSZ; wi++)
            pd[(tl + wi) * TT + tl] = sv[wi] * inv;
    }

    const int d4 = tid & 63;    // float4 column within d-chunk
    const int tg = tid >> 6;    // t-group (8 t's each)
    const int tb = tg * 8;

    unsigned long long acc[16];
#pragma unroll
    for (int j = 0; j < 16; j++) acc[j] = 0ULL;

    const ulonglong2* xsq = reinterpret_cast<const ulonglong2*>(xs);
    const float4* pdq = reinterpret_cast<const float4*>(pd);
    float4* o4 = reinterpret_cast<float4*>(out);
    // base index of out[t0+tb, b, d-chunk] as float4, copy half (offset 0)
    const size_t ocopy = ((size_t)(t0 + tb) * B_DIM + b) * (2 * D_DIM / 4) + (d0 >> 2) + d4;

#define ROW_STEP(r, DO_COPY)                                             \
    {                                                                    \
        int row = tb + (r);                                              \
        ulonglong2 xv = xsq[row * 64 + d4];                              \
        float4 p0 = pdq[row * 8 + tg * 2 + 0];                           \
        float4 p1 = pdq[row * 8 + tg * 2 + 1];                           \
        unsigned long long q0 = dup2(p0.x), q1 = dup2(p0.y);             \
        unsigned long long q2 = dup2(p0.z), q3 = dup2(p0.w);             \
        unsigned long long q4 = dup2(p1.x), q5 = dup2(p1.y);             \
        unsigned long long q6 = dup2(p1.z), q7 = dup2(p1.w);             \
        fma2(acc[0],  xv.x, q0); fma2(acc[1],  xv.y, q0);                \
        fma2(acc[2],  xv.x, q1); fma2(acc[3],  xv.y, q1);                \
        fma2(acc[4],  xv.x, q2); fma2(acc[5],  xv.y, q2);                \
        fma2(acc[6],  xv.x, q3); fma2(acc[7],  xv.y, q3);                \
        fma2(acc[8],  xv.x, q4); fma2(acc[9],  xv.y, q4);                \
        fma2(acc[10], xv.x, q5); fma2(acc[11], xv.y, q5);                \
        fma2(acc[12], xv.x, q6); fma2(acc[13], xv.y, q6);                \
        fma2(acc[14], xv.x, q7); fma2(acc[15], xv.y, q7);                \
        if (DO_COPY) {                                                   \
            float2 lo = u2f(xv.x), hi = u2f(xv.y);                       \
            __stcs(&o4[ocopy + (size_t)((r) - 16) * B_DIM * (2 * D_DIM / 4)], \
                   make_float4(lo.x, lo.y, hi.x, hi.y));                 \
        }                                                                \
    }

    // rows needed at step r: tb+r. Stage s covers rows [16s, 16s+15].
    cp_wait<2>();            // stages 0,1 complete (rows 0..31)
    __syncthreads();         // pd scatter + stage data visible to all
#pragma unroll
    for (int r = 0; r < 8; r++) ROW_STEP(r, false);

    cp_wait<1>();            // stage 2 (rows 32..47)
    __syncthreads();
#pragma unroll
    for (int r = 8; r < 16; r++) ROW_STEP(r, false);
#pragma unroll
    for (int r = 16; r < 24; r++) ROW_STEP(r, true);   // xv here == x[t0+tb+r-16]

    cp_wait<0>();            // stage 3 (rows 48..63)
    __syncthreads();
#pragma unroll
    for (int r = 24; r < 40; r++) ROW_STEP(r, false);
#undef ROW_STEP

    // attn half: out[t, b, D + d]
#pragma unroll
    for (int j = 0; j < 8; j++) {
        int t = t0 + tb + j;
        float2 lo = u2f(acc[2 * j]);
        float2 hi = u2f(acc[2 * j + 1]);
        __stcs(&o4[((size_t)t * B_DIM + b) * (2 * D_DIM / 4) + (D_DIM / 4) + (d0 >> 2) + d4],
               make_float4(lo.x, lo.y, hi.x, hi.y));
    }
}

// ---------------------------------------------------------------------------
extern "C" void kernel_launch(void* const* d_in, const int* in_sizes, int n_in,
                              void* d_out, int out_size) {
    const float* x  = reinterpret_cast<const float*>(d_in[0]);
    const float* w  = reinterpret_cast<const float*>(d_in[1]);
    const float* bb = reinterpret_cast<const float*>(d_in[2]);
    float* out = reinterpret_cast<float*>(d_out);

    const int smem_bytes = HR * DC * 4 + HR * TT * 4;   // 64KB + 8KB
    cudaFuncSetAttribute(k_attn, cudaFuncAttributeMaxDynamicSharedMemorySize, smem_bytes);

    k_dots<<<(T_DIM * B_DIM) / 8, 256>>>(x, w);
    dim3 grid(D_DIM / DC, T_DIM / TT, B_DIM);
    k_attn<<<grid, 256, smem_bytes>>>(x, bb, out);
}

// round 4
// speedup vs baseline: 1.7169x; 1.0667x over previous
#include <cuda_runtime.h>
#include <cuda_bf16.h>
#include <cstdint>

#define T_DIM 512
#define B_DIM 16
#define D_DIM 1024
#define WIN   16
#define WSZ   33           // window taps = 2*WIN+1
#define TT    32           // t-tile per block in attn kernel
#define DC    128          // d-chunk (floats) per block in attn kernel
#define HR    (TT + 2*WIN) // halo rows = 64

// Scratch (no cudaMalloc allowed)
__device__ float g_a[T_DIM * B_DIM];
__device__ float g_c[T_DIM * B_DIM];

// ---------------------------------------------------------------------------
// Kernel A: pure dot products a = x·w_cur, c = x·w_seq per (t,b) row.
// One warp per row; leaves x L2-resident for k_attn.
// ---------------------------------------------------------------------------
__global__ void k_dots(const float* __restrict__ x, const float* __restrict__ w) {
    int warp = (blockIdx.x << 3) + (threadIdx.x >> 5);   // row r = t*16 + b
    int lane = threadIdx.x & 31;
    const float4* xr = reinterpret_cast<const float4*>(x) + (size_t)warp * 256;
    const float4* wc = reinterpret_cast<const float4*>(w);
    const float4* ws = wc + 256;

    float4 xv[8];
#pragma unroll
    for (int i = 0; i < 8; i++) xv[i] = xr[lane + i * 32];   // front-load, MLP=8

    float sa = 0.f, sc = 0.f;
#pragma unroll
    for (int i = 0; i < 8; i++) {
        int k = lane + i * 32;
        float4 a4 = __ldg(&wc[k]);
        float4 c4 = __ldg(&ws[k]);
        sa += xv[i].x * a4.x + xv[i].y * a4.y + xv[i].z * a4.z + xv[i].w * a4.w;
        sc += xv[i].x * c4.x + xv[i].y * c4.y + xv[i].z * c4.z + xv[i].w * c4.w;
    }
#pragma unroll
    for (int off = 16; off; off >>= 1) {
        sa += __shfl_xor_sync(0xFFFFFFFFu, sa, off);
        sc += __shfl_xor_sync(0xFFFFFFFFu, sc, off);
    }
    if (lane == 0) { g_a[warp] = sa; g_c[warp] = sc; }
}

// ---------------------------------------------------------------------------
// packed f32x2 + cp.async helpers
// ---------------------------------------------------------------------------
__device__ __forceinline__ void fma2(unsigned long long& a,
                                     unsigned long long xv,
                                     unsigned long long pp) {
    asm("fma.rn.f32x2 %0, %1, %2, %0;" : "+l"(a) : "l"(xv), "l"(pp));
}
__device__ __forceinline__ float2 u2f(unsigned long long v) {
    float2 r;
    asm("mov.b64 {%0,%1}, %2;" : "=f"(r.x), "=f"(r.y) : "l"(v));
    return r;
}
__device__ __forceinline__ unsigned long long dup2(float p) {
    unsigned long long u;
    asm("mov.b64 %0, {%1, %1};" : "=l"(u) : "f"(p));
    return u;
}
__device__ __forceinline__ void cp16(void* s, const void* g) {
    unsigned sa = (unsigned)__cvta_generic_to_shared(s);
    asm volatile("cp.async.cg.shared.global [%0], [%1], 16;" :: "r"(sa), "l"(g));
}
__device__ __forceinline__ void cp_commit() {
    asm volatile("cp.async.commit_group;");
}
template <int N>
__device__ __forceinline__ void cp_wait() {
    asm volatile("cp.async.wait_group %0;" :: "n"(N));
}

// ---------------------------------------------------------------------------
// Kernel B (fused softmax + windowed sum + x-copy):
//   out[t,b,0:D]  = x[t,b,:]
//   out[t,b,D:2D] = sum_w softmax_w(a+c+b0) * x[clip(t-16+w),b,:]
// Block = (d-chunk 128, t-tile 32, b). 40KB smem -> 5 CTAs/SM.
// Thread: float4 d-column (32 cols), 4 consecutive t accumulators.
// ---------------------------------------------------------------------------
__global__ void __launch_bounds__(256, 5)
k_attn(const float* __restrict__ x, const float* __restrict__ bb,
       float* __restrict__ out) {
    extern __shared__ float smem[];
    float* xs = smem;                      // 64*128 f = 32KB
    float* pd = smem + HR * DC;            // 64*32 f = 8KB;  pd[row*TT + tl]
    float* sc_a = pd + HR * TT;            // 32 f
    float* sc_c = sc_a + TT;               // 64 f (c window, -inf for invalid)

    const int tid = threadIdx.x;
    const int d0 = blockIdx.x * DC;
    const int t0 = blockIdx.y * TT;
    const int b  = blockIdx.z;

    // ---- issue all 4 cp.async stages (16 rows x 128 floats each) ----
    const float4* x4 = reinterpret_cast<const float4*>(x);
    float4* xs4 = reinterpret_cast<float4*>(xs);
#pragma unroll
    for (int s = 0; s < 4; s++) {
#pragma unroll
        for (int k = 0; k < 2; k++) {
            int idx = s * 512 + k * 256 + tid;    // f4 index within tile
            int row = idx >> 5;
            int col = idx & 31;
            int gr = t0 - WIN + row;
            gr = gr < 0 ? 0 : (gr > T_DIM - 1 ? T_DIM - 1 : gr);
            cp16(&xs4[idx], &x4[((size_t)gr * B_DIM + b) * (D_DIM / 4) + (d0 >> 2) + col]);
        }
        cp_commit();
    }

    // ---- preload a/c windows + zero pd while TMA-class loads fly ----
    if (tid < TT) sc_a[tid] = g_a[(t0 + tid) * B_DIM + b];
    else if (tid < TT + HR) {
        int i = tid - TT;
        int gr = t0 - WIN + i;
        sc_c[i] = (gr >= 0 && gr < T_DIM) ? g_c[gr * B_DIM + b] : -INFINITY;
    }
#pragma unroll
    for (int i = tid; i < HR * TT; i += 256) pd[i] = 0.f;
    __syncthreads();

    // ---- warp 0: softmax for the 32 t's, scatter diagonally into pd ----
    if (tid < 32) {
        const int tl = tid;
        const float base = sc_a[tl] + bb[0];
        float sv[WSZ];
        float m = -INFINITY;
#pragma unroll
        for (int wi = 0; wi < WSZ; wi++) {
            float v = base + sc_c[tl + wi];       // -inf stays -inf
            sv[wi] = v;
            m = fmaxf(m, v);
        }
        float sum = 0.f;
#pragma unroll
        for (int wi = 0; wi < WSZ; wi++) {
            float e = (sv[wi] == -INFINITY) ? 0.f : __expf(sv[wi] - m);
            sv[wi] = e;
            sum += e;
        }
        float inv = 1.f / sum;
#pragma unroll
        for (int wi = 0; wi < WSZ; wi++)
            pd[(tl + wi) * TT + tl] = sv[wi] * inv;
    }

    const int d4 = tid & 31;    // float4 column within d-chunk
    const int tg = tid >> 5;    // t-group (4 t's each), uniform per warp
    const int tb = tg * 4;

    unsigned long long acc[8];
#pragma unroll
    for (int j = 0; j < 8; j++) acc[j] = 0ULL;

    const ulonglong2* xsq = reinterpret_cast<const ulonglong2*>(xs);
    const float4* pdq = reinterpret_cast<const float4*>(pd);
    float4* o4 = reinterpret_cast<float4*>(out);
    // out row stride = 2D floats = 512 f4; copy half at offset 0
    const size_t ocopy = ((size_t)(t0 + tb) * B_DIM + b) * 512 + (d0 >> 2) + d4;

#define ROW_STEP(r, DO_COPY)                                              \
    {                                                                     \
        int row = tb + (r);                                               \
        ulonglong2 xv = xsq[row * 32 + d4];                               \
        float4 p4 = pdq[row * 8 + tg];   /* pd[row][tb..tb+3], bcast */   \
        unsigned long long q0 = dup2(p4.x), q1 = dup2(p4.y);              \
        unsigned long long q2 = dup2(p4.z), q3 = dup2(p4.w);              \
        fma2(acc[0], xv.x, q0); fma2(acc[1], xv.y, q0);                   \
        fma2(acc[2], xv.x, q1); fma2(acc[3], xv.y, q1);                   \
        fma2(acc[4], xv.x, q2); fma2(acc[5], xv.y, q2);                   \
        fma2(acc[6], xv.x, q3); fma2(acc[7], xv.y, q3);                   \
        if (DO_COPY) {                                                    \
            float2 lo = u2f(xv.x), hi = u2f(xv.y);                        \
            __stcs(&o4[ocopy + (size_t)((r) - 16) * B_DIM * 512],         \
                   make_float4(lo.x, lo.y, hi.x, hi.y));                  \
        }                                                                 \
    }

    // step r touches row tb+r (max tb=28). Stage s covers rows [16s,16s+15].
    cp_wait<2>();            // rows 0..31 ready
    __syncthreads();         // + pd scatter visible
#pragma unroll
    for (int r = 0; r < 4; r++) ROW_STEP(r, false);   // max row 31

    cp_wait<1>();            // rows 0..47 ready
    __syncthreads();
#pragma unroll
    for (int r = 4; r < 16; r++) ROW_STEP(r, false);  // max row 43
#pragma unroll
    for (int r = 16; r < 20; r++) ROW_STEP(r, true);  // xv == x[t0+tb+r-16]

    cp_wait<0>();            // all rows ready
    __syncthreads();
#pragma unroll
    for (int r = 20; r < 36; r++) ROW_STEP(r, false); // max row 63
#undef ROW_STEP

    // attn half: out[t, b, D + d]
#pragma unroll
    for (int j = 0; j < 4; j++) {
        int t = t0 + tb + j;
        float2 lo = u2f(acc[2 * j]);
        float2 hi = u2f(acc[2 * j + 1]);
        __stcs(&o4[((size_t)t * B_DIM + b) * 512 + (D_DIM / 4) + (d0 >> 2) + d4],
               make_float4(lo.x, lo.y, hi.x, hi.y));
    }
}

// ---------------------------------------------------------------------------
extern "C" void kernel_launch(void* const* d_in, const int* in_sizes, int n_in,
                              void* d_out, int out_size) {
    const float* x  = reinterpret_cast<const float*>(d_in[0]);
    const float* w  = reinterpret_cast<const float*>(d_in[1]);
    const float* bb = reinterpret_cast<const float*>(d_in[2]);
    float* out = reinterpret_cast<float*>(d_out);

    const int smem_bytes = (HR * DC + HR * TT + TT + HR) * 4 + 16;
    cudaFuncSetAttribute(k_attn, cudaFuncAttributeMaxDynamicSharedMemorySize, smem_bytes);

    k_dots<<<(T_DIM * B_DIM) / 8, 256>>>(x, w);
    dim3 grid(D_DIM / DC, T_DIM / TT, B_DIM);
    k_attn<<<grid, 256, smem_bytes>>>(x, bb, out);
}